// round 9
// baseline (speedup 1.0000x reference)
#include <cuda_runtime.h>
#include <cuda_bf16.h>
#include <math.h>

#define M_ROWS   65536
#define D_DIM    64
#define K_CODES  4096
#define KS       88                       // padded K stride (bf16), 80 used
#define NSTEP    5                        // k16 steps (5*16 = 80)
#define MT       128                      // rows per CTA
#define NT       64                       // codes per chunk
#define NCH      (K_CODES / NT)           // 64
#define MTILES   (M_ROWS / MT)            // 512
#define A_BYTES  (MT * KS * 2)            // 22528
#define B_BYTES  (NT * KS * 2)            // 11264
#define A_UNITS  (A_BYTES / 16)           // 1408
#define B_UNITS  (B_BYTES / 16)           // 704
#define SMEM_DYN (A_BYTES + 2 * B_BYTES)  // 45056

// ---- global scratch (static __device__; no runtime allocs) ----
__device__ __align__(16) unsigned char g_A[(size_t)M_ROWS * KS * 2];   // ~11.5 MB
__device__ __align__(16) unsigned char g_B[(size_t)K_CODES * KS * 2];  // ~0.7 MB
__device__ float g_c[K_CODES];                                         // 0.5*||e||^2
__device__ float g_partials[MTILES];

#define NEG_INF (-3.402823466e38f)

// ======================= helpers (compute_103-safe) =======================
__device__ __forceinline__ unsigned smem_u32(const void* p) {
    unsigned a;
    asm("{ .reg .u64 t; cvta.to.shared.u64 t, %1; cvt.u32.u64 %0, t; }" : "=r"(a) : "l"(p));
    return a;
}
__device__ __forceinline__ unsigned pack_bf16x2(float lo, float hi) {
    unsigned r;
    asm("cvt.rn.bf16x2.f32 %0, %1, %2;" : "=r"(r) : "f"(hi), "f"(lo));
    return r;  // low 16 bits (first in memory) = lo
}
__device__ __forceinline__ void cp_async16(unsigned saddr, const void* gaddr) {
    asm volatile("cp.async.cg.shared.global [%0], [%1], 16;" :: "r"(saddr), "l"(gaddr) : "memory");
}
__device__ __forceinline__ void cp_commit() {
    asm volatile("cp.async.commit_group;" ::: "memory");
}
template <int N>
__device__ __forceinline__ void cp_wait() {
    asm volatile("cp.async.wait_group %0;" :: "n"(N) : "memory");
}
__device__ __forceinline__ void ldsm_x4(unsigned* r, unsigned addr) {
    asm volatile("ldmatrix.sync.aligned.m8n8.x4.shared.b16 {%0,%1,%2,%3}, [%4];"
                 : "=r"(r[0]), "=r"(r[1]), "=r"(r[2]), "=r"(r[3]) : "r"(addr));
}
__device__ __forceinline__ void mma16816(float* c, const unsigned* a, const unsigned* b) {
    asm volatile(
        "mma.sync.aligned.m16n8k16.row.col.f32.bf16.bf16.f32 "
        "{%0,%1,%2,%3}, {%4,%5,%6,%7}, {%8,%9}, {%0,%1,%2,%3};"
        : "+f"(c[0]), "+f"(c[1]), "+f"(c[2]), "+f"(c[3])
        : "r"(a[0]), "r"(a[1]), "r"(a[2]), "r"(a[3]), "r"(b[0]), "r"(b[1]));
}
// first k-step: c-input = 0 (avoids per-chunk accumulator zeroing)
__device__ __forceinline__ void mma16816_z(float* c, const unsigned* a, const unsigned* b) {
    asm volatile(
        "mma.sync.aligned.m16n8k16.row.col.f32.bf16.bf16.f32 "
        "{%0,%1,%2,%3}, {%4,%5,%6,%7}, {%8,%9}, {%10,%10,%10,%10};"
        : "=f"(c[0]), "=f"(c[1]), "=f"(c[2]), "=f"(c[3])
        : "r"(a[0]), "r"(a[1]), "r"(a[2]), "r"(a[3]), "r"(b[0]), "r"(b[1]), "f"(0.0f));
}
// ordered insert into sorted-desc top-3 of plain floats
__device__ __forceinline__ void ins3f(float* v, float nv) {
    if (nv > v[0])      { v[2] = v[1]; v[1] = v[0]; v[0] = nv; }
    else if (nv > v[1]) { v[2] = v[1]; v[1] = nv; }
    else if (nv > v[2]) { v[2] = nv; }
}
__device__ __forceinline__ void merge3f_shfl(float* v, int off) {
    float ov[3];
    #pragma unroll
    for (int j = 0; j < 3; j++) ov[j] = __shfl_xor_sync(0xffffffffu, v[j], off);
    #pragma unroll
    for (int j = 0; j < 3; j++) ins3f(v, ov[j]);
}

// ===================== prep kernels =====================
__global__ void vq_prep_c(const float* __restrict__ cb) {
    int k    = blockIdx.x * 8 + (threadIdx.x >> 5);
    int lane = threadIdx.x & 31;
    float2 v = reinterpret_cast<const float2*>(cb + (size_t)k * D_DIM)[lane];
    float s  = v.x * v.x + v.y * v.y;
    #pragma unroll
    for (int o = 16; o > 0; o >>= 1) s += __shfl_down_sync(0xffffffffu, s, o);
    if (lane == 0) g_c[k] = 0.5f * s;
}

// A row m: [zh(0:64) | 1,1 @64,65 | 0 pad to 88]
__global__ void vq_prep_A(const float* __restrict__ z) {
    int m = blockIdx.x * 8 + (threadIdx.x >> 5);
    int l = threadIdx.x & 31;
    float2 x = reinterpret_cast<const float2*>(z + (size_t)m * D_DIM)[l];
    unsigned H = pack_bf16x2(x.x, x.y);
    unsigned* row = reinterpret_cast<unsigned*>(g_A) + (size_t)m * (KS / 2);
    row[l] = H;
    if (l == 0) row[32] = pack_bf16x2(1.0f, 1.0f);
    if (l >= 1 && l <= 11) row[32 + l] = 0u;
}

// B row k: [eh(0:64) | -c_hi,-c_lo @64,65 | 0 pad to 88]
__global__ void vq_prep_B(const float* __restrict__ cb) {
    int k = blockIdx.x * 8 + (threadIdx.x >> 5);
    int l = threadIdx.x & 31;
    float2 x = reinterpret_cast<const float2*>(cb + (size_t)k * D_DIM)[l];
    unsigned H = pack_bf16x2(x.x, x.y);
    unsigned* row = reinterpret_cast<unsigned*>(g_B) + (size_t)k * (KS / 2);
    row[l] = H;
    if (l == 0) {
        float c  = g_c[k];
        float ch = __bfloat162float(__float2bfloat16(c));
        row[32] = pack_bf16x2(-ch, -(c - ch));
    }
    if (l >= 1 && l <= 11) row[32 + l] = 0u;
}

// ===================== main fused HMMA GEMM + argmax =====================
// acc: ACC(nb, p): nb = 16-code block (0..3), p = 8-code sub-block (0..1)
// [0,1] = rowhalf 0 (row l>>2), [2,3] = rowhalf 1 (row (l>>2)+8)
#define ACC(nb, p) (&acc[((nb) * 2 + (p)) * 4])

__global__ void __launch_bounds__(256, 3)
vq_mma_kernel(float* __restrict__ out, const float* __restrict__ z_e,
              const float* __restrict__ cb, int out_size_i) {
    extern __shared__ unsigned char smem_raw[];
    __shared__ float shred[8];

    const unsigned uA  = smem_u32(smem_raw);
    const unsigned uB0 = uA + A_BYTES;
    const unsigned uB1 = uB0 + B_BYTES;

    const int tid  = threadIdx.x;
    const int w    = tid >> 5;        // warp owns rows w*16..+15
    const int l    = tid & 31;
    const int tile = blockIdx.x;

    // ---- prologue: A tile + B chunk 0, then B chunk 1 ----
    {
        const unsigned char* gA = g_A + (size_t)tile * A_BYTES;
        for (int u = tid; u < A_UNITS; u += 256) cp_async16(uA + u * 16, gA + u * 16);
        for (int u = tid; u < B_UNITS; u += 256) cp_async16(uB0 + u * 16, g_B + u * 16);
        cp_commit();
        const unsigned char* gB1 = g_B + (size_t)B_BYTES;
        for (int u = tid; u < B_UNITS; u += 256) cp_async16(uB1 + u * 16, gB1 + u * 16);
        cp_commit();
    }
    cp_wait<1>();          // A + B0 landed
    __syncthreads();

    // ---- load this warp's A rows into registers once (16 rows x 80 k) ----
    const unsigned a_lane = ((unsigned)(w * 16 + (l & 15)) * KS + (unsigned)(l >> 4) * 8) * 2;
    unsigned aA[NSTEP][4];
    #pragma unroll
    for (int s = 0; s < NSTEP; s++) ldsm_x4(aA[s], uA + a_lane + (unsigned)s * 32);

    // B ldsm lane offset within a 16-code block
    const unsigned b_lane = ((unsigned)((l >> 4) * 8 + (l & 7)) * KS
                             + (unsigned)((l >> 3) & 1) * 8) * 2;
    const unsigned C16 = 16u * KS * 2;     // +16 codes

    float acc[32];
    // 2 packed top-2 chains (rowhalf 0/1)
    float cb0 = NEG_INF, cs0 = NEG_INF, cb1 = NEG_INF, cs1 = NEG_INF;

    const unsigned lane_q = (unsigned)(l & 3);   // bits [1:0] of code10

    for (int ch = 0; ch < NCH; ch++) {
        const unsigned ub = (ch & 1) ? uB1 : uB0;

        #pragma unroll
        for (int s = 0; s < NSTEP; s++) {
            unsigned b0[4], b1[4], b2[4], b3[4];
            ldsm_x4(b0, ub + b_lane + s * 32);
            ldsm_x4(b1, ub + b_lane + C16 + s * 32);
            ldsm_x4(b2, ub + b_lane + 2 * C16 + s * 32);
            ldsm_x4(b3, ub + b_lane + 3 * C16 + s * 32);
            if (s == 0) {
                mma16816_z(ACC(0,0), aA[0], b0); mma16816_z(ACC(0,1), aA[0], b0 + 2);
                mma16816_z(ACC(1,0), aA[0], b1); mma16816_z(ACC(1,1), aA[0], b1 + 2);
                mma16816_z(ACC(2,0), aA[0], b2); mma16816_z(ACC(2,1), aA[0], b2 + 2);
                mma16816_z(ACC(3,0), aA[0], b3); mma16816_z(ACC(3,1), aA[0], b3 + 2);
            } else {
                mma16816(ACC(0,0), aA[s], b0); mma16816(ACC(0,1), aA[s], b0 + 2);
                mma16816(ACC(1,0), aA[s], b1); mma16816(ACC(1,1), aA[s], b1 + 2);
                mma16816(ACC(2,0), aA[s], b2); mma16816(ACC(2,1), aA[s], b2 + 2);
                mma16816(ACC(3,0), aA[s], b3); mma16816(ACC(3,1), aA[s], b3 + 2);
            }
        }

        // ---- fold: quad-max (cols nb*16 + q*2 + {0,1,8,9}) -> packed top-2 ----
        // code10 = ch(6) | nb(2) | q(2)
        const unsigned qb = ((unsigned)ch << 4) | lane_q;
        #pragma unroll
        for (int nb = 0; nb < 4; nb++) {
            const float* P0 = ACC(nb, 0);
            const float* P1 = ACC(nb, 1);
            const unsigned qc = qb | ((unsigned)nb << 2);
            {   // rowhalf 0
                float qm = fmaxf(fmaxf(P0[0], P0[1]), fmaxf(P1[0], P1[1]));
                float pv = __uint_as_float((__float_as_uint(qm) & 0xFFFFFC00u) | qc);
                cs0 = fmaxf(cs0, fminf(cb0, pv));
                cb0 = fmaxf(cb0, pv);
            }
            {   // rowhalf 1
                float qm = fmaxf(fmaxf(P0[2], P0[3]), fmaxf(P1[2], P1[3]));
                float pv = __uint_as_float((__float_as_uint(qm) & 0xFFFFFC00u) | qc);
                cs1 = fmaxf(cs1, fminf(cb1, pv));
                cb1 = fmaxf(cb1, pv);
            }
        }

        __syncthreads();                         // all reads of buf[ch&1] done
        if (ch + 2 < NCH) {                      // prefetch chunk ch+2 into buf[ch&1]
            const unsigned ubn = (ch & 1) ? uB1 : uB0;
            const unsigned char* gBn = g_B + (size_t)(ch + 2) * B_BYTES;
            for (int u = tid; u < B_UNITS; u += 256) cp_async16(ubn + u * 16, gBn + u * 16);
            cp_commit();
            cp_wait<1>();                        // chunk ch+1 landed
        } else if (ch + 1 < NCH) {
            cp_wait<0>();
        }
        __syncthreads();                         // visibility of prefetched data
    }

    // ---- per-row top-3 quads: promote chain top-2, quad-lane merge ----
    float* s_v0 = reinterpret_cast<float*>(smem_raw);            // [128]
    float* s_v1 = s_v0 + 128;
    float* s_v2 = s_v1 + 128;

    #pragma unroll
    for (int g = 0; g < 2; g++) {
        float tv[3];
        tv[0] = g ? cb1 : cb0;
        tv[1] = g ? cs1 : cs0;
        tv[2] = NEG_INF;
        merge3f_shfl(tv, 1);
        merge3f_shfl(tv, 2);
        if ((l & 3) == 0) {
            const int row = w * 16 + g * 8 + (l >> 2);
            s_v0[row] = tv[0]; s_v1[row] = tv[1]; s_v2[row] = tv[2];
        }
    }
    __syncthreads();

    // ---- decode, exact fp32 rescore of top-3 quads (12 codes) ----
    const size_t osz = (size_t)out_size_i;
    float lsum = 0.0f;
    if (tid < 128) {
        float tv[3];
        tv[0] = s_v0[tid]; tv[1] = s_v1[tid]; tv[2] = s_v2[tid];

        const int m = tile * MT + tid;
        const float4* zr = reinterpret_cast<const float4*>(z_e + (size_t)m * D_DIM);
        float4 zv[16];
        #pragma unroll
        for (int j = 0; j < 16; j++) zv[j] = zr[j];

        float bestv = NEG_INF;
        int   fin   = K_CODES;
        #pragma unroll
        for (int c3 = 0; c3 < 3; c3++) {
            const unsigned bits = __float_as_uint(tv[c3]) & 1023u;
            const int col0 = (int)(((bits >> 4) << 6) | (((bits >> 2) & 3u) << 4)
                                   | ((bits & 3u) << 1));
            #pragma unroll
            for (int oi = 0; oi < 4; oi++) {
                const int code = col0 + ((oi & 1) + (oi >> 1) * 8);  // +{0,1,8,9}
                const float4* er = reinterpret_cast<const float4*>(cb + (size_t)code * D_DIM);
                float s = -g_c[code];
                #pragma unroll
                for (int j = 0; j < 16; j++) {
                    float4 e = er[j];
                    s += zv[j].x * e.x + zv[j].y * e.y + zv[j].z * e.z + zv[j].w * e.w;
                }
                if (s > bestv || (s == bestv && code < fin)) { bestv = s; fin = code; }
            }
        }

        // ---- outputs ----
        const size_t MD    = (size_t)M_ROWS * D_DIM;
        const size_t base2 = MD + M_ROWS + 2;
        const float4* er = reinterpret_cast<const float4*>(cb + (size_t)fin * D_DIM);
        float4* out4 = reinterpret_cast<float4*>(out);
        float2* out2 = reinterpret_cast<float2*>(out);
        const size_t o1 = (size_t)m * D_DIM;
        const size_t o3 = base2 + (size_t)m * D_DIM;

        #pragma unroll
        for (int j = 0; j < 16; j++) {
            float4 e = er[j];
            float4 z = zv[j];
            float4 zst;
            zst.x = z.x + (e.x - z.x);
            zst.y = z.y + (e.y - z.y);
            zst.z = z.z + (e.z - z.z);
            zst.w = z.w + (e.w - z.w);
            float d0 = z.x - e.x, d1 = z.y - e.y, d2 = z.z - e.z, d3 = z.w - e.w;
            lsum += d0 * d0 + d1 * d1 + d2 * d2 + d3 * d3;
            if (o1 + (size_t)j * 4 + 4 <= osz) out4[o1 / 4 + j] = zst;
            if (o3 + (size_t)j * 4 + 4 <= osz) {
                out2[o3 / 2 + 2 * j]     = make_float2(e.x, e.y);
                out2[o3 / 2 + 2 * j + 1] = make_float2(e.z, e.w);
            }
        }
        if (MD + (size_t)m < osz) out[MD + (size_t)m] = (float)fin;
    }

    #pragma unroll
    for (int o = 16; o > 0; o >>= 1) lsum += __shfl_down_sync(0xffffffffu, lsum, o);
    if ((tid & 31) == 0) shred[w] = lsum;
    __syncthreads();
    if (tid == 0) {
        float t = 0.0f;
        #pragma unroll
        for (int i = 0; i < 8; i++) t += shred[i];
        g_partials[tile] = t;
    }
}

// ===================== finalize: vq_loss + perplexity =====================
__global__ void vq_finalize_kernel(const float* __restrict__ ema,
                                   float* __restrict__ out, int out_size_i) {
    __shared__ float red[1024];
    const size_t osz = (size_t)out_size_i;
    const int tid = threadIdx.x;

    float v = (tid < MTILES) ? g_partials[tid] : 0.0f;
    red[tid] = v;
    for (int o = 512; o > 0; o >>= 1) {
        __syncthreads();
        if (tid < o) red[tid] += red[tid + o];
    }
    __syncthreads();
    const float vq_loss = 0.25f * red[0] / (float)((size_t)M_ROWS * D_DIM);
    __syncthreads();

    float s = 0.0f;
    for (int i = tid; i < K_CODES; i += 1024) s += ema[i] + 1e-10f;
    red[tid] = s;
    for (int o = 512; o > 0; o >>= 1) {
        __syncthreads();
        if (tid < o) red[tid] += red[tid + o];
    }
    __syncthreads();
    const float S = red[0];
    __syncthreads();

    float ent = 0.0f;
    for (int i = tid; i < K_CODES; i += 1024) {
        float p = (ema[i] + 1e-10f) / S;
        ent += p * logf(p);
    }
    red[tid] = ent;
    for (int o = 512; o > 0; o >>= 1) {
        __syncthreads();
        if (tid < o) red[tid] += red[tid + o];
    }
    __syncthreads();

    if (tid == 0) {
        const size_t base = (size_t)M_ROWS * D_DIM + M_ROWS;
        if (base < osz)     out[base]     = vq_loss;
        if (base + 1 < osz) out[base + 1] = expf(-red[0]);
    }
}

extern "C" void kernel_launch(void* const* d_in, const int* in_sizes, int n_in,
                              void* d_out, int out_size) {
    const float* z_e = (const float*)d_in[0];   // (65536, 64) f32
    const float* cb  = (const float*)d_in[1];   // (4096, 64) f32
    const float* ema = (const float*)d_in[2];   // (4096,) f32
    float* out = (float*)d_out;

    cudaFuncSetAttribute(vq_mma_kernel,
                         cudaFuncAttributeMaxDynamicSharedMemorySize, SMEM_DYN);

    vq_prep_c<<<K_CODES / 8, 256>>>(cb);
    vq_prep_A<<<M_ROWS / 8, 256>>>(z_e);
    vq_prep_B<<<K_CODES / 8, 256>>>(cb);
    vq_mma_kernel<<<MTILES, 256, SMEM_DYN>>>(out, z_e, cb, out_size);
    vq_finalize_kernel<<<1, 1024>>>(ema, out, out_size);
}

// round 10
// speedup vs baseline: 1.5088x; 1.5088x over previous
#include <cuda_runtime.h>
#include <cuda_bf16.h>
#include <math.h>

#define M_ROWS   65536
#define D_DIM    64
#define K_CODES  4096
#define KS       88                       // padded K stride (bf16), 80 used
#define NSTEP    5                        // k16 steps (5*16 = 80)
#define MT       128                      // rows per CTA
#define NT       128                      // codes per chunk
#define NCH      (K_CODES / NT)           // 32
#define MTILES   (M_ROWS / MT)            // 512
#define CTA_THREADS 128
#define A_BYTES  (MT * KS * 2)            // 22528
#define B_BYTES  (NT * KS * 2)            // 22528
#define A_UNITS  (A_BYTES / 16)           // 1408
#define B_UNITS  (B_BYTES / 16)           // 1408
#define SMEM_DYN (A_BYTES + 2 * B_BYTES)  // 67584

// ---- global scratch (static __device__; no runtime allocs) ----
__device__ __align__(16) unsigned char g_A[(size_t)M_ROWS * KS * 2];   // ~11.5 MB
__device__ __align__(16) unsigned char g_B[(size_t)K_CODES * KS * 2];  // ~0.7 MB
__device__ float g_c[K_CODES];                                         // 0.5*||e||^2
__device__ float g_partials[MTILES];

#define NEG_INF (-3.402823466e38f)

// ======================= helpers (compute_103-safe) =======================
__device__ __forceinline__ unsigned smem_u32(const void* p) {
    unsigned a;
    asm("{ .reg .u64 t; cvta.to.shared.u64 t, %1; cvt.u32.u64 %0, t; }" : "=r"(a) : "l"(p));
    return a;
}
__device__ __forceinline__ unsigned pack_bf16x2(float lo, float hi) {
    unsigned r;
    asm("cvt.rn.bf16x2.f32 %0, %1, %2;" : "=r"(r) : "f"(hi), "f"(lo));
    return r;  // low 16 bits (first in memory) = lo
}
__device__ __forceinline__ void cp_async16(unsigned saddr, const void* gaddr) {
    asm volatile("cp.async.cg.shared.global [%0], [%1], 16;" :: "r"(saddr), "l"(gaddr) : "memory");
}
__device__ __forceinline__ void cp_commit() {
    asm volatile("cp.async.commit_group;" ::: "memory");
}
template <int N>
__device__ __forceinline__ void cp_wait() {
    asm volatile("cp.async.wait_group %0;" :: "n"(N) : "memory");
}
__device__ __forceinline__ void ldsm_x4(unsigned* r, unsigned addr) {
    asm volatile("ldmatrix.sync.aligned.m8n8.x4.shared.b16 {%0,%1,%2,%3}, [%4];"
                 : "=r"(r[0]), "=r"(r[1]), "=r"(r[2]), "=r"(r[3]) : "r"(addr));
}
__device__ __forceinline__ void mma16816(float* c, const unsigned* a, const unsigned* b) {
    asm volatile(
        "mma.sync.aligned.m16n8k16.row.col.f32.bf16.bf16.f32 "
        "{%0,%1,%2,%3}, {%4,%5,%6,%7}, {%8,%9}, {%0,%1,%2,%3};"
        : "+f"(c[0]), "+f"(c[1]), "+f"(c[2]), "+f"(c[3])
        : "r"(a[0]), "r"(a[1]), "r"(a[2]), "r"(a[3]), "r"(b[0]), "r"(b[1]));
}
// first k-step: c-input = 0 (avoids per-segment accumulator zeroing)
__device__ __forceinline__ void mma16816_z(float* c, const unsigned* a, const unsigned* b) {
    asm volatile(
        "mma.sync.aligned.m16n8k16.row.col.f32.bf16.bf16.f32 "
        "{%0,%1,%2,%3}, {%4,%5,%6,%7}, {%8,%9}, {%10,%10,%10,%10};"
        : "=f"(c[0]), "=f"(c[1]), "=f"(c[2]), "=f"(c[3])
        : "r"(a[0]), "r"(a[1]), "r"(a[2]), "r"(a[3]), "r"(b[0]), "r"(b[1]), "f"(0.0f));
}
// ordered insert into sorted-desc top-3 of plain floats
__device__ __forceinline__ void ins3f(float* v, float nv) {
    if (nv > v[0])      { v[2] = v[1]; v[1] = v[0]; v[0] = nv; }
    else if (nv > v[1]) { v[2] = v[1]; v[1] = nv; }
    else if (nv > v[2]) { v[2] = nv; }
}
__device__ __forceinline__ void merge3f_shfl(float* v, int off) {
    float ov[3];
    #pragma unroll
    for (int j = 0; j < 3; j++) ov[j] = __shfl_xor_sync(0xffffffffu, v[j], off);
    #pragma unroll
    for (int j = 0; j < 3; j++) ins3f(v, ov[j]);
}

// ===================== prep kernels =====================
__global__ void vq_prep_c(const float* __restrict__ cb) {
    int k    = blockIdx.x * 8 + (threadIdx.x >> 5);
    int lane = threadIdx.x & 31;
    float2 v = reinterpret_cast<const float2*>(cb + (size_t)k * D_DIM)[lane];
    float s  = v.x * v.x + v.y * v.y;
    #pragma unroll
    for (int o = 16; o > 0; o >>= 1) s += __shfl_down_sync(0xffffffffu, s, o);
    if (lane == 0) g_c[k] = 0.5f * s;
}

// A row m: [zh(0:64) | 1,1 @64,65 | 0 pad to 88]
__global__ void vq_prep_A(const float* __restrict__ z) {
    int m = blockIdx.x * 8 + (threadIdx.x >> 5);
    int l = threadIdx.x & 31;
    float2 x = reinterpret_cast<const float2*>(z + (size_t)m * D_DIM)[l];
    unsigned H = pack_bf16x2(x.x, x.y);
    unsigned* row = reinterpret_cast<unsigned*>(g_A) + (size_t)m * (KS / 2);
    row[l] = H;
    if (l == 0) row[32] = pack_bf16x2(1.0f, 1.0f);
    if (l >= 1 && l <= 11) row[32 + l] = 0u;
}

// B row k: [eh(0:64) | -c_hi,-c_lo @64,65 | 0 pad to 88]
__global__ void vq_prep_B(const float* __restrict__ cb) {
    int k = blockIdx.x * 8 + (threadIdx.x >> 5);
    int l = threadIdx.x & 31;
    float2 x = reinterpret_cast<const float2*>(cb + (size_t)k * D_DIM)[l];
    unsigned H = pack_bf16x2(x.x, x.y);
    unsigned* row = reinterpret_cast<unsigned*>(g_B) + (size_t)k * (KS / 2);
    row[l] = H;
    if (l == 0) {
        float c  = g_c[k];
        float ch = __bfloat162float(__float2bfloat16(c));
        row[32] = pack_bf16x2(-ch, -(c - ch));
    }
    if (l >= 1 && l <= 11) row[32 + l] = 0u;
}

// ===================== main fused HMMA GEMM + argmax =====================
// 4 warps = 2 row-groups (rg: 64 rows) x 2 col-groups (wc: 64 of the 128 chunk cols)
// Per chunk: 4 segments of 16 cols. acc: ACC(ra,p) p=8-code sub-block;
// [0,1] = rowhalf 0 (row ra*16 + l>>2), [2,3] = rowhalf 1 (+8)
#define ACC(ra, p) (&acc[((ra) * 2 + (p)) * 4])

__global__ void __launch_bounds__(CTA_THREADS, 3)
vq_mma_kernel(float* __restrict__ out, const float* __restrict__ z_e,
              const float* __restrict__ cb, int out_size_i) {
    extern __shared__ unsigned char smem_raw[];
    __shared__ float shred[4];

    const unsigned uA  = smem_u32(smem_raw);
    const unsigned uB0 = uA + A_BYTES;
    const unsigned uB1 = uB0 + B_BYTES;

    const int tid  = threadIdx.x;
    const int w    = tid >> 5;
    const int l    = tid & 31;
    const int rg   = w >> 1;          // row group: rows rg*64..+63
    const int wc   = w & 1;           // col group: chunk cols wc*64..+63
    const int tile = blockIdx.x;

    // ---- prologue: A tile + B chunk 0, then B chunk 1 ----
    {
        const unsigned char* gA = g_A + (size_t)tile * A_BYTES;
        for (int u = tid; u < A_UNITS; u += CTA_THREADS) cp_async16(uA + u * 16, gA + u * 16);
        for (int u = tid; u < B_UNITS; u += CTA_THREADS) cp_async16(uB0 + u * 16, g_B + u * 16);
        cp_commit();
        const unsigned char* gB1 = g_B + (size_t)B_BYTES;
        for (int u = tid; u < B_UNITS; u += CTA_THREADS) cp_async16(uB1 + u * 16, gB1 + u * 16);
        cp_commit();
    }
    cp_wait<1>();          // A + B0 landed
    __syncthreads();

    // ---- load this warp's 64 A rows into registers once (80 k each) ----
    unsigned aA[4][NSTEP][4];        // 80 regs
    {
        const unsigned a_lane = ((unsigned)(rg * 64 + (l & 15)) * KS
                                 + (unsigned)(l >> 4) * 8) * 2;
        #pragma unroll
        for (int ra = 0; ra < 4; ra++)
            #pragma unroll
            for (int s = 0; s < NSTEP; s++)
                ldsm_x4(aA[ra][s], uA + a_lane + (unsigned)ra * (16u * KS * 2)
                                       + (unsigned)s * 32);
    }

    // B ldsm lane offset within a 16-code block
    const unsigned b_lane = ((unsigned)((l >> 4) * 8 + (l & 7)) * KS
                             + (unsigned)((l >> 3) & 1) * 8) * 2;

    // 8 packed top-2 chains: g = ra*2 + rowhalf
    float cb_[8], cs_[8];
    #pragma unroll
    for (int i = 0; i < 8; i++) { cb_[i] = NEG_INF; cs_[i] = NEG_INF; }

    const unsigned lane_q = (unsigned)(l & 3);

    for (int ch = 0; ch < NCH; ch++) {
        const unsigned ub = (ch & 1) ? uB1 : uB0;

        #pragma unroll
        for (int seg = 0; seg < 4; seg++) {
            const unsigned cbase = ub + b_lane
                                 + (unsigned)(wc * 64 + seg * 16) * (KS * 2);
            float acc[32];
            #pragma unroll
            for (int s = 0; s < NSTEP; s++) {
                unsigned b[4];
                ldsm_x4(b, cbase + s * 32);
                if (s == 0) {
                    #pragma unroll
                    for (int ra = 0; ra < 4; ra++) {
                        mma16816_z(ACC(ra, 0), aA[ra][0], b);
                        mma16816_z(ACC(ra, 1), aA[ra][0], b + 2);
                    }
                } else {
                    #pragma unroll
                    for (int ra = 0; ra < 4; ra++) {
                        mma16816(ACC(ra, 0), aA[ra][s], b);
                        mma16816(ACC(ra, 1), aA[ra][s], b + 2);
                    }
                }
            }

            // ---- fold: quad-max {c0,c0+1,c0+8,c0+9} -> packed top-2 chains ----
            // code10 = ch(5) | wc(1) | seg(2) | q(2)
            const unsigned qc = ((unsigned)ch << 5) | ((unsigned)wc << 4)
                              | ((unsigned)seg << 2) | lane_q;
            #pragma unroll
            for (int ra = 0; ra < 4; ra++) {
                const float* P0 = ACC(ra, 0);
                const float* P1 = ACC(ra, 1);
                {   // rowhalf 0
                    float qm = fmaxf(fmaxf(P0[0], P0[1]), fmaxf(P1[0], P1[1]));
                    float pv = __uint_as_float((__float_as_uint(qm) & 0xFFFFFC00u) | qc);
                    const int g = ra * 2;
                    cs_[g] = fmaxf(cs_[g], fminf(cb_[g], pv));
                    cb_[g] = fmaxf(cb_[g], pv);
                }
                {   // rowhalf 1
                    float qm = fmaxf(fmaxf(P0[2], P0[3]), fmaxf(P1[2], P1[3]));
                    float pv = __uint_as_float((__float_as_uint(qm) & 0xFFFFFC00u) | qc);
                    const int g = ra * 2 + 1;
                    cs_[g] = fmaxf(cs_[g], fminf(cb_[g], pv));
                    cb_[g] = fmaxf(cb_[g], pv);
                }
            }
        }

        __syncthreads();                         // all reads of buf[ch&1] done
        if (ch + 2 < NCH) {                      // prefetch chunk ch+2 into buf[ch&1]
            const unsigned ubn = (ch & 1) ? uB1 : uB0;
            const unsigned char* gBn = g_B + (size_t)(ch + 2) * B_BYTES;
            for (int u = tid; u < B_UNITS; u += CTA_THREADS) cp_async16(ubn + u * 16, gBn + u * 16);
            cp_commit();
            cp_wait<1>();                        // chunk ch+1 landed
        } else if (ch + 1 < NCH) {
            cp_wait<0>();
        }
        __syncthreads();                         // visibility of prefetched data
    }

    // ---- per-row top-3 quads: promote chain top-2, quad-lane merge ----
    float* s_v0 = reinterpret_cast<float*>(smem_raw);            // [2][128]
    float* s_v1 = s_v0 + 256;
    float* s_v2 = s_v1 + 256;

    #pragma unroll
    for (int g = 0; g < 8; g++) {
        float tv[3];
        tv[0] = cb_[g]; tv[1] = cs_[g]; tv[2] = NEG_INF;
        merge3f_shfl(tv, 1);
        merge3f_shfl(tv, 2);
        if ((l & 3) == 0) {
            const int ra = g >> 1, rh = g & 1;
            const int row = rg * 64 + ra * 16 + rh * 8 + (l >> 2);
            const int ix  = wc * 128 + row;
            s_v0[ix] = tv[0]; s_v1[ix] = tv[1]; s_v2[ix] = tv[2];
        }
    }
    __syncthreads();

    // ---- merge col-groups, decode, exact fp32 rescore of 12 codes ----
    const size_t osz = (size_t)out_size_i;
    float lsum = 0.0f;
    {
        float tv[3];
        tv[0] = s_v0[tid]; tv[1] = s_v1[tid]; tv[2] = s_v2[tid];
        ins3f(tv, s_v0[128 + tid]);
        ins3f(tv, s_v1[128 + tid]);
        ins3f(tv, s_v2[128 + tid]);

        const int m = tile * MT + tid;
        const float4* zr = reinterpret_cast<const float4*>(z_e + (size_t)m * D_DIM);
        float4 zv[16];
        #pragma unroll
        for (int j = 0; j < 16; j++) zv[j] = zr[j];

        float bestv = NEG_INF;
        int   fin   = K_CODES;
        #pragma unroll
        for (int c3 = 0; c3 < 3; c3++) {
            const unsigned bits = __float_as_uint(tv[c3]) & 1023u;
            const int col0 = (int)(((bits >> 5) << 7) | (((bits >> 4) & 1u) << 6)
                                   | (((bits >> 2) & 3u) << 4) | ((bits & 3u) << 1));
            #pragma unroll
            for (int oi = 0; oi < 4; oi++) {
                const int code = col0 + ((oi & 1) + (oi >> 1) * 8);  // +{0,1,8,9}
                const float4* er = reinterpret_cast<const float4*>(cb + (size_t)code * D_DIM);
                float s = -g_c[code];
                #pragma unroll
                for (int j = 0; j < 16; j++) {
                    float4 e = er[j];
                    s += zv[j].x * e.x + zv[j].y * e.y + zv[j].z * e.z + zv[j].w * e.w;
                }
                if (s > bestv || (s == bestv && code < fin)) { bestv = s; fin = code; }
            }
        }

        // ---- outputs ----
        const size_t MD    = (size_t)M_ROWS * D_DIM;
        const size_t base2 = MD + M_ROWS + 2;
        const float4* er = reinterpret_cast<const float4*>(cb + (size_t)fin * D_DIM);
        float4* out4 = reinterpret_cast<float4*>(out);
        float2* out2 = reinterpret_cast<float2*>(out);
        const size_t o1 = (size_t)m * D_DIM;
        const size_t o3 = base2 + (size_t)m * D_DIM;

        #pragma unroll
        for (int j = 0; j < 16; j++) {
            float4 e = er[j];
            float4 z = zv[j];
            float4 zst;
            zst.x = z.x + (e.x - z.x);
            zst.y = z.y + (e.y - z.y);
            zst.z = z.z + (e.z - z.z);
            zst.w = z.w + (e.w - z.w);
            float d0 = z.x - e.x, d1 = z.y - e.y, d2 = z.z - e.z, d3 = z.w - e.w;
            lsum += d0 * d0 + d1 * d1 + d2 * d2 + d3 * d3;
            if (o1 + (size_t)j * 4 + 4 <= osz) out4[o1 / 4 + j] = zst;
            if (o3 + (size_t)j * 4 + 4 <= osz) {
                out2[o3 / 2 + 2 * j]     = make_float2(e.x, e.y);
                out2[o3 / 2 + 2 * j + 1] = make_float2(e.z, e.w);
            }
        }
        if (MD + (size_t)m < osz) out[MD + (size_t)m] = (float)fin;
    }

    #pragma unroll
    for (int o = 16; o > 0; o >>= 1) lsum += __shfl_down_sync(0xffffffffu, lsum, o);
    if ((tid & 31) == 0) shred[w] = lsum;
    __syncthreads();
    if (tid == 0) {
        float t = 0.0f;
        #pragma unroll
        for (int i = 0; i < 4; i++) t += shred[i];
        g_partials[tile] = t;
    }
}

// ===================== finalize: vq_loss + perplexity =====================
__global__ void vq_finalize_kernel(const float* __restrict__ ema,
                                   float* __restrict__ out, int out_size_i) {
    __shared__ float red[1024];
    const size_t osz = (size_t)out_size_i;
    const int tid = threadIdx.x;

    float v = (tid < MTILES) ? g_partials[tid] : 0.0f;
    red[tid] = v;
    for (int o = 512; o > 0; o >>= 1) {
        __syncthreads();
        if (tid < o) red[tid] += red[tid + o];
    }
    __syncthreads();
    const float vq_loss = 0.25f * red[0] / (float)((size_t)M_ROWS * D_DIM);
    __syncthreads();

    float s = 0.0f;
    for (int i = tid; i < K_CODES; i += 1024) s += ema[i] + 1e-10f;
    red[tid] = s;
    for (int o = 512; o > 0; o >>= 1) {
        __syncthreads();
        if (tid < o) red[tid] += red[tid + o];
    }
    __syncthreads();
    const float S = red[0];
    __syncthreads();

    float ent = 0.0f;
    for (int i = tid; i < K_CODES; i += 1024) {
        float p = (ema[i] + 1e-10f) / S;
        ent += p * logf(p);
    }
    red[tid] = ent;
    for (int o = 512; o > 0; o >>= 1) {
        __syncthreads();
        if (tid < o) red[tid] += red[tid + o];
    }
    __syncthreads();

    if (tid == 0) {
        const size_t base = (size_t)M_ROWS * D_DIM + M_ROWS;
        if (base < osz)     out[base]     = vq_loss;
        if (base + 1 < osz) out[base + 1] = expf(-red[0]);
    }
}

extern "C" void kernel_launch(void* const* d_in, const int* in_sizes, int n_in,
                              void* d_out, int out_size) {
    const float* z_e = (const float*)d_in[0];   // (65536, 64) f32
    const float* cb  = (const float*)d_in[1];   // (4096, 64) f32
    const float* ema = (const float*)d_in[2];   // (4096,) f32
    float* out = (float*)d_out;

    cudaFuncSetAttribute(vq_mma_kernel,
                         cudaFuncAttributeMaxDynamicSharedMemorySize, SMEM_DYN);

    vq_prep_c<<<K_CODES / 8, 256>>>(cb);
    vq_prep_A<<<M_ROWS / 8, 256>>>(z_e);
    vq_prep_B<<<K_CODES / 8, 256>>>(cb);
    vq_mma_kernel<<<MTILES, CTA_THREADS, SMEM_DYN>>>(out, z_e, cb, out_size);
    vq_finalize_kernel<<<1, 1024>>>(ema, out, out_size);
}

// round 12
// speedup vs baseline: 2.1316x; 1.4128x over previous
#include <cuda_runtime.h>
#include <cuda_bf16.h>
#include <math.h>

#define M_ROWS   65536
#define D_DIM    64
#define K_CODES  4096
#define KS       88                       // padded K stride (bf16), 80 used
#define NSTEP    5                        // k16 steps (5*16 = 80)
#define MT       64                       // rows per CTA
#define MTILES   (M_ROWS / MT)            // 1024
#define CTA_THREADS 128
#define NCB16    (K_CODES / 16)           // 256 16-code blocks
#define A_BYTES  (MT * KS * 2)            // 11264
#define A_UNITS  (A_BYTES / 16)           // 704
#define SMEM_DYN A_BYTES

// ---- global scratch (static __device__; no runtime allocs) ----
__device__ __align__(16) unsigned char g_A[(size_t)M_ROWS * KS * 2];       // ~11.5 MB
__device__ __align__(16) unsigned char g_Bf[(size_t)NCB16 * NSTEP * 32 * 16]; // 655 KB frag-packed
__device__ float g_c[K_CODES];                                             // 0.5*||e||^2
__device__ float g_partials[MTILES];

#define NEG_INF (-3.402823466e38f)

// ======================= helpers (compute_103-safe) =======================
__device__ __forceinline__ unsigned smem_u32(const void* p) {
    unsigned a;
    asm("{ .reg .u64 t; cvta.to.shared.u64 t, %1; cvt.u32.u64 %0, t; }" : "=r"(a) : "l"(p));
    return a;
}
__device__ __forceinline__ unsigned pack_bf16x2(float lo, float hi) {
    unsigned r;
    asm("cvt.rn.bf16x2.f32 %0, %1, %2;" : "=r"(r) : "f"(hi), "f"(lo));
    return r;  // low 16 bits (first in memory) = lo
}
__device__ __forceinline__ void cp_async16(unsigned saddr, const void* gaddr) {
    asm volatile("cp.async.cg.shared.global [%0], [%1], 16;" :: "r"(saddr), "l"(gaddr) : "memory");
}
__device__ __forceinline__ void cp_commit() {
    asm volatile("cp.async.commit_group;" ::: "memory");
}
template <int N>
__device__ __forceinline__ void cp_wait() {
    asm volatile("cp.async.wait_group %0;" :: "n"(N) : "memory");
}
__device__ __forceinline__ void ldsm_x4(unsigned* r, unsigned addr) {
    asm volatile("ldmatrix.sync.aligned.m8n8.x4.shared.b16 {%0,%1,%2,%3}, [%4];"
                 : "=r"(r[0]), "=r"(r[1]), "=r"(r[2]), "=r"(r[3]) : "r"(addr));
}
__device__ __forceinline__ void mma16816(float* c, const unsigned* a, const unsigned* b) {
    asm volatile(
        "mma.sync.aligned.m16n8k16.row.col.f32.bf16.bf16.f32 "
        "{%0,%1,%2,%3}, {%4,%5,%6,%7}, {%8,%9}, {%0,%1,%2,%3};"
        : "+f"(c[0]), "+f"(c[1]), "+f"(c[2]), "+f"(c[3])
        : "r"(a[0]), "r"(a[1]), "r"(a[2]), "r"(a[3]), "r"(b[0]), "r"(b[1]));
}
__device__ __forceinline__ void mma16816_z(float* c, const unsigned* a, const unsigned* b) {
    asm volatile(
        "mma.sync.aligned.m16n8k16.row.col.f32.bf16.bf16.f32 "
        "{%0,%1,%2,%3}, {%4,%5,%6,%7}, {%8,%9}, {%10,%10,%10,%10};"
        : "=f"(c[0]), "=f"(c[1]), "=f"(c[2]), "=f"(c[3])
        : "r"(a[0]), "r"(a[1]), "r"(a[2]), "r"(a[3]), "r"(b[0]), "r"(b[1]), "f"(0.0f));
}
__device__ __forceinline__ void ins3f(float* v, float nv) {
    if (nv > v[0])      { v[2] = v[1]; v[1] = v[0]; v[0] = nv; }
    else if (nv > v[1]) { v[2] = v[1]; v[1] = nv; }
    else if (nv > v[2]) { v[2] = nv; }
}
__device__ __forceinline__ void merge3f_shfl(float* v, int off) {
    float ov[3];
    #pragma unroll
    for (int j = 0; j < 3; j++) ov[j] = __shfl_xor_sync(0xffffffffu, v[j], off);
    #pragma unroll
    for (int j = 0; j < 3; j++) ins3f(v, ov[j]);
}

// ===================== prep kernels =====================
__global__ void vq_prep_c(const float* __restrict__ cb) {
    int k    = blockIdx.x * 8 + (threadIdx.x >> 5);
    int lane = threadIdx.x & 31;
    float2 v = reinterpret_cast<const float2*>(cb + (size_t)k * D_DIM)[lane];
    float s  = v.x * v.x + v.y * v.y;
    #pragma unroll
    for (int o = 16; o > 0; o >>= 1) s += __shfl_down_sync(0xffffffffu, s, o);
    if (lane == 0) g_c[k] = 0.5f * s;
}

// A row m: [zh(0:64) | 1,1 @64,65 | 0 pad to 88]
__global__ void vq_prep_A(const float* __restrict__ z) {
    int m = blockIdx.x * 8 + (threadIdx.x >> 5);
    int l = threadIdx.x & 31;
    float2 x = reinterpret_cast<const float2*>(z + (size_t)m * D_DIM)[l];
    unsigned H = pack_bf16x2(x.x, x.y);
    unsigned* row = reinterpret_cast<unsigned*>(g_A) + (size_t)m * (KS / 2);
    row[l] = H;
    if (l == 0) row[32] = pack_bf16x2(1.0f, 1.0f);
    if (l >= 1 && l <= 11) row[32 + l] = 0u;
}

// virtual B element (n = code, k = 0..79): e[n][k] for k<64, bias at 64/65, else 0
__device__ __forceinline__ float bval(const float* cb, int n, int k) {
    if (k < 64) return cb[n * D_DIM + k];
    if (k == 64) { float c = g_c[n]; return -__bfloat162float(__float2bfloat16(c)); }
    if (k == 65) { float c = g_c[n]; float ch = __bfloat162float(__float2bfloat16(c)); return -(c - ch); }
    return 0.0f;
}

// fragment-packed B: word idx = ((cb16*5 + s)*32 + lane)*4 + q
// quad q, lane l -> code = cb16*16 + (q>=2?8:0) + (l>>2), k = s*16 + (q&1?8:0) + (l&3)*2
__global__ void vq_prep_Bf(const float* __restrict__ cb) {
    int idx = blockIdx.x * 256 + threadIdx.x;     // 163840 words
    int q    = idx & 3;
    int t    = idx >> 2;
    int lane = t & 31;  t >>= 5;
    int s    = t % NSTEP;
    int cb16 = t / NSTEP;
    int n = cb16 * 16 + ((q >> 1) ? 8 : 0) + (lane >> 2);
    int k = s * 16 + ((q & 1) ? 8 : 0) + (lane & 3) * 2;
    float v0 = bval(cb, n, k);
    float v1 = bval(cb, n, k + 1);
    reinterpret_cast<unsigned*>(g_Bf)[idx] = pack_bf16x2(v0, v1);
}

// ===================== main fused HMMA GEMM + argmax =====================
// 4 warps = 2 row-groups (rg: 32 rows) x 2 col-groups (wc: cb16 blocks wc*128..+127)
// acc: ACC(ra,p): ra = 16-row block, p = 8-code half;
// [0,1] = rowhalf 0 (row ra*16 + l>>2), [2,3] = rowhalf 1 (+8)
#define ACC(ra, p) (&acc[((ra) * 2 + (p)) * 4])

__global__ void __launch_bounds__(CTA_THREADS, 4)
vq_mma_kernel(float* __restrict__ out, const float* __restrict__ z_e,
              const float* __restrict__ cb, int out_size_i) {
    extern __shared__ unsigned char smem_raw[];
    __shared__ float shred[4];

    const unsigned uA = smem_u32(smem_raw);
    const int tid  = threadIdx.x;
    const int w    = tid >> 5;
    const int l    = tid & 31;
    const int rg   = w >> 1;          // rows rg*32..+31
    const int wc   = w & 1;           // cb16 blocks wc*128..+127
    const int tile = blockIdx.x;

    // ---- stage A tile (only cp.async in the kernel) ----
    {
        const unsigned char* gA = g_A + (size_t)tile * A_BYTES;
        for (int u = tid; u < A_UNITS; u += CTA_THREADS) cp_async16(uA + u * 16, gA + u * 16);
        cp_commit();
    }
    cp_wait<0>();
    __syncthreads();

    // ---- this warp's 32 A rows -> registers (80 k each) ----
    unsigned aA[2][NSTEP][4];        // 40 regs
    {
        const unsigned a_lane = ((unsigned)(rg * 32 + (l & 15)) * KS
                                 + (unsigned)(l >> 4) * 8) * 2;
        #pragma unroll
        for (int ra = 0; ra < 2; ra++)
            #pragma unroll
            for (int s = 0; s < NSTEP; s++)
                ldsm_x4(aA[ra][s], uA + a_lane + (unsigned)ra * (16u * KS * 2)
                                       + (unsigned)s * 32);
    }

    // 4 packed top-2 chains: g = ra*2 + rowhalf
    float cb_[4], cs_[4];
    #pragma unroll
    for (int i = 0; i < 4; i++) { cb_[i] = NEG_INF; cs_[i] = NEG_INF; }

    const unsigned lane_q = (unsigned)(l & 3);
    const uint4* bf0 = reinterpret_cast<const uint4*>(g_Bf)
                     + (size_t)(wc * 128) * NSTEP * 32 + l;

    // ---- main loop: no smem, no barriers; B frags streamed from L2 ----
    #pragma unroll 2
    for (int blk = 0; blk < 128; blk++) {
        const int gb = wc * 128 + blk;                  // global cb16 index
        const uint4* bp = bf0 + (size_t)blk * (NSTEP * 32);

        uint4 bv[NSTEP];
        #pragma unroll
        for (int s = 0; s < NSTEP; s++) bv[s] = __ldg(bp + s * 32);

        float acc[16];
        #pragma unroll
        for (int s = 0; s < NSTEP; s++) {
            const unsigned* b = reinterpret_cast<const unsigned*>(&bv[s]);
            if (s == 0) {
                mma16816_z(ACC(0,0), aA[0][0], b); mma16816_z(ACC(0,1), aA[0][0], b + 2);
                mma16816_z(ACC(1,0), aA[1][0], b); mma16816_z(ACC(1,1), aA[1][0], b + 2);
            } else {
                mma16816(ACC(0,0), aA[0][s], b); mma16816(ACC(0,1), aA[0][s], b + 2);
                mma16816(ACC(1,0), aA[1][s], b); mma16816(ACC(1,1), aA[1][s], b + 2);
            }
        }

        // fold: quad-max {c0,c0+1,c0+8,c0+9}, code10 = gb(8) | q(2)
        const unsigned qc = ((unsigned)gb << 2) | lane_q;
        #pragma unroll
        for (int ra = 0; ra < 2; ra++) {
            const float* P0 = ACC(ra, 0);
            const float* P1 = ACC(ra, 1);
            {   // rowhalf 0
                float qm = fmaxf(fmaxf(P0[0], P0[1]), fmaxf(P1[0], P1[1]));
                float pv = __uint_as_float((__float_as_uint(qm) & 0xFFFFFC00u) | qc);
                const int g = ra * 2;
                cs_[g] = fmaxf(cs_[g], fminf(cb_[g], pv));
                cb_[g] = fmaxf(cb_[g], pv);
            }
            {   // rowhalf 1
                float qm = fmaxf(fmaxf(P0[2], P0[3]), fmaxf(P1[2], P1[3]));
                float pv = __uint_as_float((__float_as_uint(qm) & 0xFFFFFC00u) | qc);
                const int g = ra * 2 + 1;
                cs_[g] = fmaxf(cs_[g], fminf(cb_[g], pv));
                cb_[g] = fmaxf(cb_[g], pv);
            }
        }
    }

    // ---- per-row top-3 quads: promote chain top-2, quad-lane merge ----
    __syncthreads();   // A smem no longer needed; reuse for results
    float* s_v0 = reinterpret_cast<float*>(smem_raw);            // [2][64]
    float* s_v1 = s_v0 + 128;
    float* s_v2 = s_v1 + 128;

    #pragma unroll
    for (int g = 0; g < 4; g++) {
        float tv[3];
        tv[0] = cb_[g]; tv[1] = cs_[g]; tv[2] = NEG_INF;
        merge3f_shfl(tv, 1);
        merge3f_shfl(tv, 2);
        if ((l & 3) == 0) {
            const int ra = g >> 1, rh = g & 1;
            const int row = rg * 32 + ra * 16 + rh * 8 + (l >> 2);
            const int ix  = wc * 64 + row;
            s_v0[ix] = tv[0]; s_v1[ix] = tv[1]; s_v2[ix] = tv[2];
        }
    }
    __syncthreads();

    // ---- merge col-groups, decode, exact fp32 rescore of 12 codes ----
    const size_t osz = (size_t)out_size_i;
    float lsum = 0.0f;
    if (tid < MT) {
        float tv[3];
        tv[0] = s_v0[tid]; tv[1] = s_v1[tid]; tv[2] = s_v2[tid];
        ins3f(tv, s_v0[64 + tid]);
        ins3f(tv, s_v1[64 + tid]);
        ins3f(tv, s_v2[64 + tid]);

        const int m = tile * MT + tid;
        const float4* zr = reinterpret_cast<const float4*>(z_e + (size_t)m * D_DIM);
        float4 zv[16];
        #pragma unroll
        for (int j = 0; j < 16; j++) zv[j] = zr[j];

        float bestv = NEG_INF;
        int   fin   = K_CODES;
        #pragma unroll
        for (int c3 = 0; c3 < 3; c3++) {
            const unsigned bits = __float_as_uint(tv[c3]) & 1023u;
            const int col0 = (int)((bits >> 2) * 16 + (bits & 3u) * 2);
            #pragma unroll
            for (int oi = 0; oi < 4; oi++) {
                const int code = col0 + ((oi & 1) + (oi >> 1) * 8);  // +{0,1,8,9}
                const float4* er = reinterpret_cast<const float4*>(cb + (size_t)code * D_DIM);
                float s = -g_c[code];
                #pragma unroll
                for (int j = 0; j < 16; j++) {
                    float4 e = er[j];
                    s += zv[j].x * e.x + zv[j].y * e.y + zv[j].z * e.z + zv[j].w * e.w;
                }
                if (s > bestv || (s == bestv && code < fin)) { bestv = s; fin = code; }
            }
        }

        // ---- outputs ----
        const size_t MD    = (size_t)M_ROWS * D_DIM;
        const size_t base2 = MD + M_ROWS + 2;
        const float4* er = reinterpret_cast<const float4*>(cb + (size_t)fin * D_DIM);
        float4* out4 = reinterpret_cast<float4*>(out);
        float2* out2 = reinterpret_cast<float2*>(out);
        const size_t o1 = (size_t)m * D_DIM;
        const size_t o3 = base2 + (size_t)m * D_DIM;

        #pragma unroll
        for (int j = 0; j < 16; j++) {
            float4 e = er[j];
            float4 z = zv[j];
            float4 zst;
            zst.x = z.x + (e.x - z.x);
            zst.y = z.y + (e.y - z.y);
            zst.z = z.z + (e.z - z.z);
            zst.w = z.w + (e.w - z.w);
            float d0 = z.x - e.x, d1 = z.y - e.y, d2 = z.z - e.z, d3 = z.w - e.w;
            lsum += d0 * d0 + d1 * d1 + d2 * d2 + d3 * d3;
            if (o1 + (size_t)j * 4 + 4 <= osz) out4[o1 / 4 + j] = zst;
            if (o3 + (size_t)j * 4 + 4 <= osz) {
                out2[o3 / 2 + 2 * j]     = make_float2(e.x, e.y);
                out2[o3 / 2 + 2 * j + 1] = make_float2(e.z, e.w);
            }
        }
        if (MD + (size_t)m < osz) out[MD + (size_t)m] = (float)fin;
    }

    #pragma unroll
    for (int o = 16; o > 0; o >>= 1) lsum += __shfl_down_sync(0xffffffffu, lsum, o);
    if ((tid & 31) == 0) shred[w] = lsum;
    __syncthreads();
    if (tid == 0) {
        float t = 0.0f;
        #pragma unroll
        for (int i = 0; i < 4; i++) t += shred[i];
        g_partials[tile] = t;
    }
}

// ===================== finalize: vq_loss + perplexity =====================
__global__ void vq_finalize_kernel(const float* __restrict__ ema,
                                   float* __restrict__ out, int out_size_i) {
    __shared__ float red[1024];
    const size_t osz = (size_t)out_size_i;
    const int tid = threadIdx.x;

    float v = (tid < MTILES) ? g_partials[tid] : 0.0f;
    red[tid] = v;
    for (int o = 512; o > 0; o >>= 1) {
        __syncthreads();
        if (tid < o) red[tid] += red[tid + o];
    }
    __syncthreads();
    const float vq_loss = 0.25f * red[0] / (float)((size_t)M_ROWS * D_DIM);
    __syncthreads();

    float s = 0.0f;
    for (int i = tid; i < K_CODES; i += 1024) s += ema[i] + 1e-10f;
    red[tid] = s;
    for (int o = 512; o > 0; o >>= 1) {
        __syncthreads();
        if (tid < o) red[tid] += red[tid + o];
    }
    __syncthreads();
    const float S = red[0];
    __syncthreads();

    float ent = 0.0f;
    for (int i = tid; i < K_CODES; i += 1024) {
        float p = (ema[i] + 1e-10f) / S;
        ent += p * logf(p);
    }
    red[tid] = ent;
    for (int o = 512; o > 0; o >>= 1) {
        __syncthreads();
        if (tid < o) red[tid] += red[tid + o];
    }
    __syncthreads();

    if (tid == 0) {
        const size_t base = (size_t)M_ROWS * D_DIM + M_ROWS;
        if (base < osz)     out[base]     = vq_loss;
        if (base + 1 < osz) out[base + 1] = expf(-red[0]);
    }
}

extern "C" void kernel_launch(void* const* d_in, const int* in_sizes, int n_in,
                              void* d_out, int out_size) {
    const float* z_e = (const float*)d_in[0];   // (65536, 64) f32
    const float* cb  = (const float*)d_in[1];   // (4096, 64) f32
    const float* ema = (const float*)d_in[2];   // (4096,) f32
    float* out = (float*)d_out;

    cudaFuncSetAttribute(vq_mma_kernel,
                         cudaFuncAttributeMaxDynamicSharedMemorySize, SMEM_DYN);

    vq_prep_c<<<K_CODES / 8, 256>>>(cb);
    vq_prep_A<<<M_ROWS / 8, 256>>>(z_e);
    vq_prep_Bf<<<(NCB16 * NSTEP * 32 * 4) / 256, 256>>>(cb);
    vq_mma_kernel<<<MTILES, CTA_THREADS, SMEM_DYN>>>(out, z_e, cb, out_size);
    vq_finalize_kernel<<<1, 1024>>>(ema, out, out_size);
}

// round 13
// speedup vs baseline: 2.3005x; 1.0792x over previous
#include <cuda_runtime.h>
#include <cuda_bf16.h>
#include <math.h>

#define M_ROWS   65536
#define D_DIM    64
#define K_CODES  4096
#define KS       72                       // padded K stride (bf16), 64 used; 144B row -> conflict-free ldsm
#define NSTEP    4                        // k16 steps (4*16 = 64)
#define MT       64                       // rows per CTA
#define MTILES   (M_ROWS / MT)            // 1024
#define CTA_THREADS 128
#define NCB16    (K_CODES / 16)           // 256 16-code blocks
#define A_BYTES  (MT * KS * 2)            // 9216
#define A_UNITS  (A_BYTES / 16)           // 576
#define SMEM_DYN A_BYTES

// ---- global scratch (static __device__; no runtime allocs) ----
__device__ __align__(16) unsigned char g_A[(size_t)M_ROWS * KS * 2];          // ~9.4 MB
__device__ __align__(16) unsigned char g_Bf[(size_t)NCB16 * NSTEP * 32 * 16]; // 512 KB frag-packed
__device__ float4 g_Cfq[NCB16 * 4];                                           // -c seeds per (block, quad)
__device__ float g_c[K_CODES];                                                // 0.5*||e||^2
__device__ float g_partials[MTILES];

#define NEG_INF (-3.402823466e38f)

// ======================= helpers (compute_103-safe) =======================
__device__ __forceinline__ unsigned smem_u32(const void* p) {
    unsigned a;
    asm("{ .reg .u64 t; cvta.to.shared.u64 t, %1; cvt.u32.u64 %0, t; }" : "=r"(a) : "l"(p));
    return a;
}
__device__ __forceinline__ unsigned pack_bf16x2(float lo, float hi) {
    unsigned r;
    asm("cvt.rn.bf16x2.f32 %0, %1, %2;" : "=r"(r) : "f"(hi), "f"(lo));
    return r;  // low 16 bits (first in memory) = lo
}
__device__ __forceinline__ void cp_async16(unsigned saddr, const void* gaddr) {
    asm volatile("cp.async.cg.shared.global [%0], [%1], 16;" :: "r"(saddr), "l"(gaddr) : "memory");
}
__device__ __forceinline__ void cp_commit() {
    asm volatile("cp.async.commit_group;" ::: "memory");
}
template <int N>
__device__ __forceinline__ void cp_wait() {
    asm volatile("cp.async.wait_group %0;" :: "n"(N) : "memory");
}
__device__ __forceinline__ void ldsm_x4(unsigned* r, unsigned addr) {
    asm volatile("ldmatrix.sync.aligned.m8n8.x4.shared.b16 {%0,%1,%2,%3}, [%4];"
                 : "=r"(r[0]), "=r"(r[1]), "=r"(r[2]), "=r"(r[3]) : "r"(addr));
}
__device__ __forceinline__ void mma16816(float* c, const unsigned* a, const unsigned* b) {
    asm volatile(
        "mma.sync.aligned.m16n8k16.row.col.f32.bf16.bf16.f32 "
        "{%0,%1,%2,%3}, {%4,%5,%6,%7}, {%8,%9}, {%0,%1,%2,%3};"
        : "+f"(c[0]), "+f"(c[1]), "+f"(c[2]), "+f"(c[3])
        : "r"(a[0]), "r"(a[1]), "r"(a[2]), "r"(a[3]), "r"(b[0]), "r"(b[1]));
}
__device__ __forceinline__ void ins3f(float* v, float nv) {
    if (nv > v[0])      { v[2] = v[1]; v[1] = v[0]; v[0] = nv; }
    else if (nv > v[1]) { v[2] = v[1]; v[1] = nv; }
    else if (nv > v[2]) { v[2] = nv; }
}
__device__ __forceinline__ void merge3f_shfl(float* v, int off) {
    float ov[3];
    #pragma unroll
    for (int j = 0; j < 3; j++) ov[j] = __shfl_xor_sync(0xffffffffu, v[j], off);
    #pragma unroll
    for (int j = 0; j < 3; j++) ins3f(v, ov[j]);
}

// ===================== prep kernels =====================
__global__ void vq_prep_c(const float* __restrict__ cb) {
    int k    = blockIdx.x * 8 + (threadIdx.x >> 5);
    int lane = threadIdx.x & 31;
    float2 v = reinterpret_cast<const float2*>(cb + (size_t)k * D_DIM)[lane];
    float s  = v.x * v.x + v.y * v.y;
    #pragma unroll
    for (int o = 16; o > 0; o >>= 1) s += __shfl_down_sync(0xffffffffu, s, o);
    if (lane == 0) g_c[k] = 0.5f * s;
}

// -c seeds: g_Cfq[gb*4+q] = {-c[gb*16+q*2], -c[+1], -c[gb*16+8+q*2], -c[+1]}
__global__ void vq_prep_Cf() {
    int t  = threadIdx.x;           // 1024 threads
    int gb = t >> 2, q = t & 3;
    int b  = gb * 16 + q * 2;
    g_Cfq[t] = make_float4(-g_c[b], -g_c[b + 1], -g_c[b + 8], -g_c[b + 9]);
}

// A row m: [zh(0:64) | 0 pad to 72]
__global__ void vq_prep_A(const float* __restrict__ z) {
    int m = blockIdx.x * 8 + (threadIdx.x >> 5);
    int l = threadIdx.x & 31;
    float2 x = reinterpret_cast<const float2*>(z + (size_t)m * D_DIM)[l];
    unsigned H = pack_bf16x2(x.x, x.y);
    unsigned* row = reinterpret_cast<unsigned*>(g_A) + (size_t)m * (KS / 2);
    row[l] = H;
    if (l < 4) row[32 + l] = 0u;
}

// fragment-packed B: word idx = ((cb16*4 + s)*32 + lane)*4 + q
// quad q, lane l -> code = cb16*16 + (q>=2?8:0) + (l>>2), k = s*16 + (q&1?8:0) + (l&3)*2
__global__ void vq_prep_Bf(const float* __restrict__ cb) {
    int idx = blockIdx.x * 256 + threadIdx.x;     // 131072 words
    int q    = idx & 3;
    int t    = idx >> 2;
    int lane = t & 31;  t >>= 5;
    int s    = t % NSTEP;
    int cb16 = t / NSTEP;
    int n = cb16 * 16 + ((q >> 1) ? 8 : 0) + (lane >> 2);
    int k = s * 16 + ((q & 1) ? 8 : 0) + (lane & 3) * 2;
    float v0 = cb[n * D_DIM + k];
    float v1 = cb[n * D_DIM + k + 1];
    reinterpret_cast<unsigned*>(g_Bf)[idx] = pack_bf16x2(v0, v1);
}

// ===================== main fused HMMA GEMM + argmax =====================
// 4 warps = 2 row-groups (rg: 32 rows) x 2 col-groups (wc: cb16 blocks wc*128..+127)
// acc: ACC(ra,p): ra = 16-row block, p = 8-code half;
// [0,1] = rowhalf 0 (row ra*16 + l>>2) cols {c0,c0+1}, [2,3] = rowhalf 1 (+8)
#define ACC(ra, p) (&acc[((ra) * 2 + (p)) * 4])

__global__ void __launch_bounds__(CTA_THREADS, 4)
vq_mma_kernel(float* __restrict__ out, const float* __restrict__ z_e,
              const float* __restrict__ cb, int out_size_i) {
    extern __shared__ unsigned char smem_raw[];
    __shared__ float shred[4];

    const unsigned uA = smem_u32(smem_raw);
    const int tid  = threadIdx.x;
    const int w    = tid >> 5;
    const int l    = tid & 31;
    const int rg   = w >> 1;          // rows rg*32..+31
    const int wc   = w & 1;           // cb16 blocks wc*128..+127
    const int tile = blockIdx.x;

    // ---- stage A tile (only cp.async in the kernel) ----
    {
        const unsigned char* gA = g_A + (size_t)tile * A_BYTES;
        for (int u = tid; u < A_UNITS; u += CTA_THREADS) cp_async16(uA + u * 16, gA + u * 16);
        cp_commit();
    }
    cp_wait<0>();
    __syncthreads();

    // ---- this warp's 32 A rows -> registers (64 k each) ----
    unsigned aA[2][NSTEP][4];        // 32 regs
    {
        const unsigned a_lane = ((unsigned)(rg * 32 + (l & 15)) * KS
                                 + (unsigned)(l >> 4) * 8) * 2;
        #pragma unroll
        for (int ra = 0; ra < 2; ra++)
            #pragma unroll
            for (int s = 0; s < NSTEP; s++)
                ldsm_x4(aA[ra][s], uA + a_lane + (unsigned)ra * (16u * KS * 2)
                                       + (unsigned)s * 32);
    }

    // 4 packed top-2 chains: g = ra*2 + rowhalf
    float cb_[4], cs_[4];
    #pragma unroll
    for (int i = 0; i < 4; i++) { cb_[i] = NEG_INF; cs_[i] = NEG_INF; }

    const unsigned lane_q = (unsigned)(l & 3);
    const uint4* bf0 = reinterpret_cast<const uint4*>(g_Bf)
                     + (size_t)(wc * 128) * NSTEP * 32 + l;

    // ---- main loop: no smem, no barriers; B frags + C seeds streamed from L2 ----
    #pragma unroll 2
    for (int blk = 0; blk < 128; blk++) {
        const int gb = wc * 128 + blk;                  // global cb16 index
        const uint4* bp = bf0 + (size_t)blk * (NSTEP * 32);

        const float4 cf = __ldg(&g_Cfq[gb * 4 + (int)lane_q]);

        uint4 bv[NSTEP];
        #pragma unroll
        for (int s = 0; s < NSTEP; s++) bv[s] = __ldg(bp + s * 32);

        // seed accumulators with -c (fp32-exact bias)
        float acc[16];
        #pragma unroll
        for (int ra = 0; ra < 2; ra++) {
            float* P0 = ACC(ra, 0);
            float* P1 = ACC(ra, 1);
            P0[0] = cf.x; P0[1] = cf.y; P0[2] = cf.x; P0[3] = cf.y;
            P1[0] = cf.z; P1[1] = cf.w; P1[2] = cf.z; P1[3] = cf.w;
        }

        #pragma unroll
        for (int s = 0; s < NSTEP; s++) {
            const unsigned* b = reinterpret_cast<const unsigned*>(&bv[s]);
            mma16816(ACC(0,0), aA[0][s], b); mma16816(ACC(0,1), aA[0][s], b + 2);
            mma16816(ACC(1,0), aA[1][s], b); mma16816(ACC(1,1), aA[1][s], b + 2);
        }

        // fold: pair-max {c0,c0+1}; pairid(11b) = gb(8) | p(1)<<2+... = gb*8 + p*4 + q
        #pragma unroll
        for (int ra = 0; ra < 2; ra++) {
            const float* P0 = ACC(ra, 0);
            const float* P1 = ACC(ra, 1);
            #pragma unroll
            for (int h = 0; h < 2; h++) {
                const int g = ra * 2 + h;
                {   // p = 0
                    float pm = fmaxf(P0[2 * h], P0[2 * h + 1]);
                    unsigned pid = ((unsigned)gb << 3) | lane_q;
                    float pv = __uint_as_float((__float_as_uint(pm) & 0xFFFFF800u) | pid);
                    cs_[g] = fmaxf(cs_[g], fminf(cb_[g], pv));
                    cb_[g] = fmaxf(cb_[g], pv);
                }
                {   // p = 1
                    float pm = fmaxf(P1[2 * h], P1[2 * h + 1]);
                    unsigned pid = ((unsigned)gb << 3) | 4u | lane_q;
                    float pv = __uint_as_float((__float_as_uint(pm) & 0xFFFFF800u) | pid);
                    cs_[g] = fmaxf(cs_[g], fminf(cb_[g], pv));
                    cb_[g] = fmaxf(cb_[g], pv);
                }
            }
        }
    }

    // ---- per-row top-3 pairs: promote chain top-2, quad-lane merge ----
    __syncthreads();   // A smem no longer needed; reuse for results
    float* s_v0 = reinterpret_cast<float*>(smem_raw);            // [2][64]
    float* s_v1 = s_v0 + 128;
    float* s_v2 = s_v1 + 128;

    #pragma unroll
    for (int g = 0; g < 4; g++) {
        float tv[3];
        tv[0] = cb_[g]; tv[1] = cs_[g]; tv[2] = NEG_INF;
        merge3f_shfl(tv, 1);
        merge3f_shfl(tv, 2);
        if ((l & 3) == 0) {
            const int ra = g >> 1, rh = g & 1;
            const int row = rg * 32 + ra * 16 + rh * 8 + (l >> 2);
            const int ix  = wc * 64 + row;
            s_v0[ix] = tv[0]; s_v1[ix] = tv[1]; s_v2[ix] = tv[2];
        }
    }
    __syncthreads();

    // ---- merge col-groups, decode, exact fp32 rescore of top-3 pairs (6 codes) ----
    const size_t osz = (size_t)out_size_i;
    float lsum = 0.0f;
    if (tid < MT) {
        float tv[3];
        tv[0] = s_v0[tid]; tv[1] = s_v1[tid]; tv[2] = s_v2[tid];
        ins3f(tv, s_v0[64 + tid]);
        ins3f(tv, s_v1[64 + tid]);
        ins3f(tv, s_v2[64 + tid]);

        const int m = tile * MT + tid;
        const float4* zr = reinterpret_cast<const float4*>(z_e + (size_t)m * D_DIM);
        float4 zv[16];
        #pragma unroll
        for (int j = 0; j < 16; j++) zv[j] = zr[j];

        float bestv = NEG_INF;
        int   fin   = K_CODES;
        #pragma unroll
        for (int c3 = 0; c3 < 3; c3++) {
            const int col0 = (int)(__float_as_uint(tv[c3]) & 2047u) * 2;
            #pragma unroll
            for (int oi = 0; oi < 2; oi++) {
                const int code = col0 + oi;
                const float4* er = reinterpret_cast<const float4*>(cb + (size_t)code * D_DIM);
                float s = -g_c[code];
                #pragma unroll
                for (int j = 0; j < 16; j++) {
                    float4 e = er[j];
                    s += zv[j].x * e.x + zv[j].y * e.y + zv[j].z * e.z + zv[j].w * e.w;
                }
                if (s > bestv || (s == bestv && code < fin)) { bestv = s; fin = code; }
            }
        }

        // ---- outputs ----
        const size_t MD    = (size_t)M_ROWS * D_DIM;
        const size_t base2 = MD + M_ROWS + 2;
        const float4* er = reinterpret_cast<const float4*>(cb + (size_t)fin * D_DIM);
        float4* out4 = reinterpret_cast<float4*>(out);
        float2* out2 = reinterpret_cast<float2*>(out);
        const size_t o1 = (size_t)m * D_DIM;
        const size_t o3 = base2 + (size_t)m * D_DIM;

        #pragma unroll
        for (int j = 0; j < 16; j++) {
            float4 e = er[j];
            float4 z = zv[j];
            float4 zst;
            zst.x = z.x + (e.x - z.x);
            zst.y = z.y + (e.y - z.y);
            zst.z = z.z + (e.z - z.z);
            zst.w = z.w + (e.w - z.w);
            float d0 = z.x - e.x, d1 = z.y - e.y, d2 = z.z - e.z, d3 = z.w - e.w;
            lsum += d0 * d0 + d1 * d1 + d2 * d2 + d3 * d3;
            if (o1 + (size_t)j * 4 + 4 <= osz) out4[o1 / 4 + j] = zst;
            if (o3 + (size_t)j * 4 + 4 <= osz) {
                out2[o3 / 2 + 2 * j]     = make_float2(e.x, e.y);
                out2[o3 / 2 + 2 * j + 1] = make_float2(e.z, e.w);
            }
        }
        if (MD + (size_t)m < osz) out[MD + (size_t)m] = (float)fin;
    }

    #pragma unroll
    for (int o = 16; o > 0; o >>= 1) lsum += __shfl_down_sync(0xffffffffu, lsum, o);
    if ((tid & 31) == 0) shred[w] = lsum;
    __syncthreads();
    if (tid == 0) {
        float t = 0.0f;
        #pragma unroll
        for (int i = 0; i < 4; i++) t += shred[i];
        g_partials[tile] = t;
    }
}

// ===================== finalize: vq_loss + perplexity =====================
__global__ void vq_finalize_kernel(const float* __restrict__ ema,
                                   float* __restrict__ out, int out_size_i) {
    __shared__ float red[1024];
    const size_t osz = (size_t)out_size_i;
    const int tid = threadIdx.x;

    float v = (tid < MTILES) ? g_partials[tid] : 0.0f;
    red[tid] = v;
    for (int o = 512; o > 0; o >>= 1) {
        __syncthreads();
        if (tid < o) red[tid] += red[tid + o];
    }
    __syncthreads();
    const float vq_loss = 0.25f * red[0] / (float)((size_t)M_ROWS * D_DIM);
    __syncthreads();

    float s = 0.0f;
    for (int i = tid; i < K_CODES; i += 1024) s += ema[i] + 1e-10f;
    red[tid] = s;
    for (int o = 512; o > 0; o >>= 1) {
        __syncthreads();
        if (tid < o) red[tid] += red[tid + o];
    }
    __syncthreads();
    const float S = red[0];
    __syncthreads();

    float ent = 0.0f;
    for (int i = tid; i < K_CODES; i += 1024) {
        float p = (ema[i] + 1e-10f) / S;
        ent += p * logf(p);
    }
    red[tid] = ent;
    for (int o = 512; o > 0; o >>= 1) {
        __syncthreads();
        if (tid < o) red[tid] += red[tid + o];
    }
    __syncthreads();

    if (tid == 0) {
        const size_t base = (size_t)M_ROWS * D_DIM + M_ROWS;
        if (base < osz)     out[base]     = vq_loss;
        if (base + 1 < osz) out[base + 1] = expf(-red[0]);
    }
}

extern "C" void kernel_launch(void* const* d_in, const int* in_sizes, int n_in,
                              void* d_out, int out_size) {
    const float* z_e = (const float*)d_in[0];   // (65536, 64) f32
    const float* cb  = (const float*)d_in[1];   // (4096, 64) f32
    const float* ema = (const float*)d_in[2];   // (4096,) f32
    float* out = (float*)d_out;

    cudaFuncSetAttribute(vq_mma_kernel,
                         cudaFuncAttributeMaxDynamicSharedMemorySize, SMEM_DYN);

    vq_prep_c<<<K_CODES / 8, 256>>>(cb);
    vq_prep_Cf<<<1, 1024>>>();
    vq_prep_A<<<M_ROWS / 8, 256>>>(z_e);
    vq_prep_Bf<<<(NCB16 * NSTEP * 32 * 4) / 256, 256>>>(cb);
    vq_mma_kernel<<<MTILES, CTA_THREADS, SMEM_DYN>>>(out, z_e, cb, out_size);
    vq_finalize_kernel<<<1, 1024>>>(ema, out, out_size);
}